// round 1
// baseline (speedup 1.0000x reference)
#include <cuda_runtime.h>
#include <math.h>

#define B_   8
#define SP   128
#define ST   64
#define SV   64
#define SEQ  256
#define DM   768
#define DL   4096
#define NH   32
#define HD   128
#define DFF  11008
#define TOK   (B_*SEQ)        // 2048
#define TVTOK (B_*(ST+SV))    // 1024

// ---------------- scratch (static device globals; no runtime allocation) ----
__device__ float g_h  [TOK*(size_t)DL];
__device__ float g_x  [TOK*(size_t)DL];
__device__ float g_q  [TOK*(size_t)DL];
__device__ float g_k  [TOK*(size_t)DL];
__device__ float g_v  [TOK*(size_t)DL];
__device__ float g_o  [TOK*(size_t)DL];
__device__ float g_act[TOK*(size_t)DFF];
__device__ float g_tv [TVTOK*(size_t)DM];
__device__ float g_tvp[TVTOK*(size_t)DL];
__device__ float g_pooled[B_*DL];
__device__ float g_t1[B_*DM];

// ---------------- embedding gather ------------------------------------------
__global__ void gather_embed_kernel(const int* __restrict__ ids,
                                    const float* __restrict__ tab,
                                    float* __restrict__ h)
{
    int t = blockIdx.x; int b = t / SP, s = t % SP;
    int id = ids[t];
    const float4* src = (const float4*)(tab + (size_t)id * DL);
    float4* dst = (float4*)(h + ((size_t)(b*SEQ + s)) * DL);
    for (int i = threadIdx.x; i < DL/4; i += blockDim.x) dst[i] = src[i];
}

__global__ void pack_tv_kernel(const float* __restrict__ text,
                               const float* __restrict__ vis,
                               float* __restrict__ tv)
{
    int t = blockIdx.x; int b = t / SP, w = t % SP;
    const float* src = (w < ST) ? (text + ((size_t)(b*ST + w)) * DM)
                                : (vis  + ((size_t)(b*SV + (w-ST))) * DM);
    float4* dst = (float4*)(tv + (size_t)t * DM);
    const float4* s4 = (const float4*)src;
    for (int i = threadIdx.x; i < DM/4; i += blockDim.x) dst[i] = s4[i];
}

__global__ void scatter_tvp_kernel(const float* __restrict__ tvp,
                                   float* __restrict__ h)
{
    int t = blockIdx.x; int b = t / SP, w = t % SP;
    const float4* src = (const float4*)(tvp + (size_t)t * DL);
    float4* dst = (float4*)(h + ((size_t)(b*SEQ + SP + w)) * DL);
    for (int i = threadIdx.x; i < DL/4; i += blockDim.x) dst[i] = src[i];
}

// ---------------- rmsnorm ---------------------------------------------------
__global__ void rmsnorm_kernel(const float* __restrict__ in,
                               const float* __restrict__ w,
                               float* __restrict__ out)
{
    int r = blockIdx.x;
    const float4* x4 = (const float4*)(in + (size_t)r * DL);
    float ss = 0.f;
    for (int i = threadIdx.x; i < DL/4; i += 256) {
        float4 v = x4[i];
        ss += v.x*v.x + v.y*v.y + v.z*v.z + v.w*v.w;
    }
    __shared__ float red[8];
    __shared__ float stot;
    int lane = threadIdx.x & 31, wp = threadIdx.x >> 5;
    for (int o = 16; o; o >>= 1) ss += __shfl_down_sync(0xffffffffu, ss, o);
    if (!lane) red[wp] = ss;
    __syncthreads();
    if (threadIdx.x == 0) {
        float s = 0.f;
        for (int i = 0; i < 8; i++) s += red[i];
        stot = rsqrtf(s / (float)DL + 1e-5f);
    }
    __syncthreads();
    float sc = stot;
    const float4* w4 = (const float4*)w;
    float4* o4 = (float4*)(out + (size_t)r * DL);
    for (int i = threadIdx.x; i < DL/4; i += 256) {
        float4 v = x4[i], ww = w4[i];
        v.x *= sc*ww.x; v.y *= sc*ww.y; v.z *= sc*ww.z; v.w *= sc*ww.w;
        o4[i] = v;
    }
}

// ---------------- generic tiled SGEMM ---------------------------------------
// EPI: 0=store  1=accumulate into C  2=store+bias  3=silu(acc)*acc2 (gate/up)
//      4=store transposed to [B,H,S,D] (for QKV)
// Assumes M % 128 == 0, N % 64 == 0, K % 16 == 0 (true for all call sites).
template <int EPI>
__global__ void __launch_bounds__(256)
gemm_kernel(const float* __restrict__ A, const float* __restrict__ B,
            const float* __restrict__ B2, const float* __restrict__ bias,
            float* __restrict__ C, int M, int N, int K)
{
    constexpr int BM = 128, BN = 64, BK = 16;
    __shared__ float As[BK][BM + 4];
    __shared__ float Bs[BK][BN];
    __shared__ float B2s[(EPI == 3) ? BK : 1][(EPI == 3) ? BN : 1];

    int tid = threadIdx.x;
    int bm = blockIdx.y * BM, bn = blockIdx.x * BN;
    int ty = tid >> 4, tx = tid & 15;

    float acc[8][4] = {};
    float acc2[8][4];
    if constexpr (EPI == 3) {
        #pragma unroll
        for (int i = 0; i < 8; i++)
            #pragma unroll
            for (int j = 0; j < 4; j++) acc2[i][j] = 0.f;
    }

    const int br = tid >> 4, bc = (tid & 15) * 4;

    for (int k0 = 0; k0 < K; k0 += BK) {
        #pragma unroll
        for (int q = 0; q < 2; q++) {
            int s = tid + q * 256;
            int ar = s >> 2, ac = (s & 3) * 4;
            float4 v = *(const float4*)(A + (size_t)(bm + ar) * K + (k0 + ac));
            As[ac + 0][ar] = v.x; As[ac + 1][ar] = v.y;
            As[ac + 2][ar] = v.z; As[ac + 3][ar] = v.w;
        }
        {
            float4 v = *(const float4*)(B + (size_t)(k0 + br) * N + (bn + bc));
            *(float4*)&Bs[br][bc] = v;
            if constexpr (EPI == 3) {
                float4 w = *(const float4*)(B2 + (size_t)(k0 + br) * N + (bn + bc));
                *(float4*)&B2s[br][bc] = w;
            }
        }
        __syncthreads();

        #pragma unroll
        for (int k = 0; k < BK; k++) {
            float4 a0 = *(const float4*)&As[k][ty * 8];
            float4 a1 = *(const float4*)&As[k][ty * 8 + 4];
            float4 bv = *(const float4*)&Bs[k][tx * 4];
            float a[8] = {a0.x, a0.y, a0.z, a0.w, a1.x, a1.y, a1.z, a1.w};
            float b[4] = {bv.x, bv.y, bv.z, bv.w};
            #pragma unroll
            for (int i = 0; i < 8; i++)
                #pragma unroll
                for (int j = 0; j < 4; j++) acc[i][j] += a[i] * b[j];
            if constexpr (EPI == 3) {
                float4 b2v = *(const float4*)&B2s[k][tx * 4];
                float b2[4] = {b2v.x, b2v.y, b2v.z, b2v.w};
                #pragma unroll
                for (int i = 0; i < 8; i++)
                    #pragma unroll
                    for (int j = 0; j < 4; j++) acc2[i][j] += a[i] * b2[j];
            }
        }
        __syncthreads();
    }

    #pragma unroll
    for (int i = 0; i < 8; i++) {
        int m = bm + ty * 8 + i;
        #pragma unroll
        for (int j = 0; j < 4; j++) {
            int n = bn + tx * 4 + j;
            if constexpr (EPI == 0) {
                C[(size_t)m * N + n] = acc[i][j];
            } else if constexpr (EPI == 1) {
                C[(size_t)m * N + n] += acc[i][j];
            } else if constexpr (EPI == 2) {
                C[(size_t)m * N + n] = acc[i][j] + bias[n];
            } else if constexpr (EPI == 3) {
                float g = acc[i][j];
                C[(size_t)m * N + n] = (g / (1.f + __expf(-g))) * acc2[i][j];
            } else { // EPI == 4 : transpose to [B,H,S,D]
                int b = m >> 8, s = m & 255;
                int hh = n >> 7, d = n & 127;
                C[(((size_t)(b * NH + hh)) * SEQ + s) * HD + d] = acc[i][j];
            }
        }
    }
}

// ---------------- RoPE (in-place on [B,H,S,D] q and k) ----------------------
__global__ void rope_kernel(float* __restrict__ q, float* __restrict__ k)
{
    int idx = blockIdx.x;            // (b*NH + h)*SEQ + s
    int s = idx & (SEQ - 1);
    int tid = threadIdx.x;           // 128: 0-63 -> q, 64-127 -> k
    float* p = (tid < 64 ? q : k) + (size_t)idx * HD;
    int d = tid & 63;
    float inv = expf(-9.210340371976184f * (float)(2 * d) * (1.0f / 128.0f));
    float ang = (float)s * inv;
    float sn, c;
    sincosf(ang, &sn, &c);
    float x1 = p[d], x2 = p[d + 64];
    p[d]      = x1 * c - x2 * sn;
    p[d + 64] = x2 * c + x1 * sn;
}

// ---------------- fused causal attention ------------------------------------
// grid (B*NH, SEQ/64), 256 threads. smem: qs[64][132], kv (max 128*68), sc[64][260]
#define ATT_SMEM ((64*132 + 8704 + 64*260) * 4)

__global__ void __launch_bounds__(256)
attention_kernel(const float* __restrict__ Q, const float* __restrict__ K,
                 const float* __restrict__ V, float* __restrict__ O)
{
    extern __shared__ float sm[];
    float* qs = sm;               // 64 x 132
    float* kv = sm + 64 * 132;    // kst[128][68] for scores, vs[64][132] for PV
    float* sc = kv + 8704;        // 64 x 260

    int bh = blockIdx.x, qt = blockIdx.y;
    const float* Qb = Q + ((size_t)bh * SEQ + qt * 64) * HD;
    const float* Kb = K + (size_t)bh * SEQ * HD;
    const float* Vb = V + (size_t)bh * SEQ * HD;
    int tid = threadIdx.x;

    for (int s2 = tid; s2 < 64 * 32; s2 += 256) {
        int r = s2 >> 5, c = (s2 & 31) * 4;
        float4 v = *(const float4*)(Qb + r * HD + c);
        float* qr = qs + r * 132 + c;
        qr[0] = v.x; qr[1] = v.y; qr[2] = v.z; qr[3] = v.w;
    }

    int ty = tid >> 4, tx = tid & 15;
    const float scale = 0.08838834764831845f; // 1/sqrt(128)

    for (int kt = 0; kt <= qt; kt++) {
        __syncthreads();  // qs ready / kv reuse safe
        for (int s2 = tid; s2 < 64 * 32; s2 += 256) {
            int r = s2 >> 5, c = (s2 & 31) * 4;
            float4 v = *(const float4*)(Kb + (kt * 64 + r) * HD + c);
            kv[(c + 0) * 68 + r] = v.x; kv[(c + 1) * 68 + r] = v.y;
            kv[(c + 2) * 68 + r] = v.z; kv[(c + 3) * 68 + r] = v.w;
        }
        __syncthreads();

        float acc[4][4] = {};
        #pragma unroll 4
        for (int d = 0; d < HD; d++) {
            float a0 = qs[(ty * 4 + 0) * 132 + d];
            float a1 = qs[(ty * 4 + 1) * 132 + d];
            float a2 = qs[(ty * 4 + 2) * 132 + d];
            float a3 = qs[(ty * 4 + 3) * 132 + d];
            float4 bv = *(const float4*)&kv[d * 68 + tx * 4];
            acc[0][0] += a0*bv.x; acc[0][1] += a0*bv.y; acc[0][2] += a0*bv.z; acc[0][3] += a0*bv.w;
            acc[1][0] += a1*bv.x; acc[1][1] += a1*bv.y; acc[1][2] += a1*bv.z; acc[1][3] += a1*bv.w;
            acc[2][0] += a2*bv.x; acc[2][1] += a2*bv.y; acc[2][2] += a2*bv.z; acc[2][3] += a2*bv.w;
            acc[3][0] += a3*bv.x; acc[3][1] += a3*bv.y; acc[3][2] += a3*bv.z; acc[3][3] += a3*bv.w;
        }

        int qg0 = qt * 64;
        #pragma unroll
        for (int i = 0; i < 4; i++) {
            int qi = ty * 4 + i; int qg = qg0 + qi;
            #pragma unroll
            for (int j = 0; j < 4; j++) {
                int kg = kt * 64 + tx * 4 + j;
                sc[qi * 260 + kg] = (kg <= qg) ? acc[i][j] * scale : -1e30f;
            }
        }
    }
    __syncthreads();

    // softmax (one row per 4-lane group)
    int row = tid >> 2, l4 = tid & 3;
    int nk = (qt + 1) * 64;
    float mx = -1e30f;
    for (int j = l4; j < nk; j += 4) mx = fmaxf(mx, sc[row * 260 + j]);
    mx = fmaxf(mx, __shfl_xor_sync(0xffffffffu, mx, 1));
    mx = fmaxf(mx, __shfl_xor_sync(0xffffffffu, mx, 2));
    float sum = 0.f;
    for (int j = l4; j < nk; j += 4) {
        float e = __expf(sc[row * 260 + j] - mx);
        sc[row * 260 + j] = e; sum += e;
    }
    sum += __shfl_xor_sync(0xffffffffu, sum, 1);
    sum += __shfl_xor_sync(0xffffffffu, sum, 2);
    float invs = 1.f / sum;
    for (int j = l4; j < nk; j += 4) sc[row * 260 + j] *= invs;
    __syncthreads();

    // PV
    float out[4][8] = {};
    for (int kt = 0; kt <= qt; kt++) {
        for (int s2 = tid; s2 < 64 * 32; s2 += 256) {
            int r = s2 >> 5, c = (s2 & 31) * 4;
            float4 v = *(const float4*)(Vb + (kt * 64 + r) * HD + c);
            *(float4*)&kv[r * 132 + c] = v;
        }
        __syncthreads();
        for (int j = 0; j < 64; j++) {
            float p0 = sc[(ty * 4 + 0) * 260 + kt * 64 + j];
            float p1 = sc[(ty * 4 + 1) * 260 + kt * 64 + j];
            float p2 = sc[(ty * 4 + 2) * 260 + kt * 64 + j];
            float p3 = sc[(ty * 4 + 3) * 260 + kt * 64 + j];
            float4 v0 = *(const float4*)&kv[j * 132 + tx * 8];
            float4 v1 = *(const float4*)&kv[j * 132 + tx * 8 + 4];
            out[0][0]+=p0*v0.x; out[0][1]+=p0*v0.y; out[0][2]+=p0*v0.z; out[0][3]+=p0*v0.w;
            out[0][4]+=p0*v1.x; out[0][5]+=p0*v1.y; out[0][6]+=p0*v1.z; out[0][7]+=p0*v1.w;
            out[1][0]+=p1*v0.x; out[1][1]+=p1*v0.y; out[1][2]+=p1*v0.z; out[1][3]+=p1*v0.w;
            out[1][4]+=p1*v1.x; out[1][5]+=p1*v1.y; out[1][6]+=p1*v1.z; out[1][7]+=p1*v1.w;
            out[2][0]+=p2*v0.x; out[2][1]+=p2*v0.y; out[2][2]+=p2*v0.z; out[2][3]+=p2*v0.w;
            out[2][4]+=p2*v1.x; out[2][5]+=p2*v1.y; out[2][6]+=p2*v1.z; out[2][7]+=p2*v1.w;
            out[3][0]+=p3*v0.x; out[3][1]+=p3*v0.y; out[3][2]+=p3*v0.z; out[3][3]+=p3*v0.w;
            out[3][4]+=p3*v1.x; out[3][5]+=p3*v1.y; out[3][6]+=p3*v1.z; out[3][7]+=p3*v1.w;
        }
        __syncthreads();
    }

    int b = bh >> 5, hh = bh & 31;
    #pragma unroll
    for (int a = 0; a < 4; a++) {
        int tokrow = qt * 64 + ty * 4 + a;
        float* dst = O + ((size_t)(b * SEQ + tokrow)) * DL + hh * HD + tx * 8;
        *(float4*)dst       = make_float4(out[a][0], out[a][1], out[a][2], out[a][3]);
        *(float4*)(dst + 4) = make_float4(out[a][4], out[a][5], out[a][6], out[a][7]);
    }
}

// ---------------- pooling + output head -------------------------------------
__global__ void pool_kernel(const float* __restrict__ x, float* __restrict__ pooled)
{
    int b = blockIdx.y;
    int d = blockIdx.x * 256 + threadIdx.x;
    const float* p = x + (size_t)b * SEQ * DL + d;
    float s = 0.f;
    for (int t = 0; t < SEQ; t++) s += p[(size_t)t * DL];
    pooled[b * DL + d] = s * (1.0f / SEQ);
}

__global__ void out1_kernel(const float* __restrict__ pooled, const float* __restrict__ W,
                            const float* __restrict__ b1, float* __restrict__ t1)
{
    int o = blockIdx.x * 8 + (threadIdx.x >> 5);
    int lane = threadIdx.x & 31;
    int b = o / DM, j = o % DM;
    const float* p = pooled + (size_t)b * DL;
    float s = 0.f;
    for (int i = lane; i < DL; i += 32) s += p[i] * W[(size_t)i * DM + j];
    for (int off = 16; off; off >>= 1) s += __shfl_down_sync(0xffffffffu, s, off);
    if (!lane) t1[o] = s + b1[j];
}

__global__ void out2_kernel(const float* __restrict__ t1, const float* __restrict__ W2,
                            const float* __restrict__ b2, float* __restrict__ y)
{
    int b = blockIdx.x;
    float s = 0.f;
    for (int j = threadIdx.x; j < DM; j += 256) s += t1[b * DM + j] * W2[j];
    __shared__ float red[8];
    int lane = threadIdx.x & 31, wp = threadIdx.x >> 5;
    for (int o = 16; o; o >>= 1) s += __shfl_down_sync(0xffffffffu, s, o);
    if (!lane) red[wp] = s;
    __syncthreads();
    if (threadIdx.x == 0) {
        float t = 0.f;
        for (int i = 0; i < 8; i++) t += red[i];
        y[b] = t + b2[0];
    }
}

// ---------------- host orchestration ----------------------------------------
extern "C" void kernel_launch(void* const* d_in, const int* in_sizes, int n_in,
                              void* d_out, int out_size)
{
    const float* text = (const float*)d_in[0];
    const float* vis  = (const float*)d_in[1];
    const int*   ids  = (const int*)  d_in[2];
    const float* inW  = (const float*)d_in[3];
    const float* inb  = (const float*)d_in[4];
    const float* etab = (const float*)d_in[5];
    const float* Wq   = (const float*)d_in[6];
    const float* Wk   = (const float*)d_in[7];
    const float* Wv   = (const float*)d_in[8];
    const float* Wo   = (const float*)d_in[9];
    const float* ln1  = (const float*)d_in[10];
    const float* ln2  = (const float*)d_in[11];
    const float* Wg   = (const float*)d_in[12];
    const float* Wu   = (const float*)d_in[13];
    const float* Wd   = (const float*)d_in[14];
    const float* fnw  = (const float*)d_in[15];
    const float* o1W  = (const float*)d_in[16];
    const float* o1b  = (const float*)d_in[17];
    const float* o2W  = (const float*)d_in[18];
    const float* o2b  = (const float*)d_in[19];
    float* y = (float*)d_out;

    float *h, *x, *q, *k, *v, *o, *act, *tv, *tvp, *pooled, *t1;
    cudaGetSymbolAddress((void**)&h,      g_h);
    cudaGetSymbolAddress((void**)&x,      g_x);
    cudaGetSymbolAddress((void**)&q,      g_q);
    cudaGetSymbolAddress((void**)&k,      g_k);
    cudaGetSymbolAddress((void**)&v,      g_v);
    cudaGetSymbolAddress((void**)&o,      g_o);
    cudaGetSymbolAddress((void**)&act,    g_act);
    cudaGetSymbolAddress((void**)&tv,     g_tv);
    cudaGetSymbolAddress((void**)&tvp,    g_tvp);
    cudaGetSymbolAddress((void**)&pooled, g_pooled);
    cudaGetSymbolAddress((void**)&t1,     g_t1);

    cudaFuncSetAttribute(attention_kernel,
                         cudaFuncAttributeMaxDynamicSharedMemorySize, ATT_SMEM);

    // --- embeddings ---
    gather_embed_kernel<<<B_ * SP, 256>>>(ids, etab, h);
    pack_tv_kernel<<<TVTOK, 256>>>(text, vis, tv);
    gemm_kernel<2><<<dim3(DL / 64, TVTOK / 128), 256>>>(tv, inW, nullptr, inb, tvp,
                                                        TVTOK, DL, DM);
    scatter_tvp_kernel<<<TVTOK, 256>>>(tvp, h);

    // --- transformer layers ---
    for (int l = 0; l < 2; l++) {
        const float* wq = Wq + (size_t)l * DL * DL;
        const float* wk = Wk + (size_t)l * DL * DL;
        const float* wv = Wv + (size_t)l * DL * DL;
        const float* wo = Wo + (size_t)l * DL * DL;
        const float* l1 = ln1 + (size_t)l * DL;
        const float* l2 = ln2 + (size_t)l * DL;
        const float* wg = Wg + (size_t)l * DL * DFF;
        const float* wu = Wu + (size_t)l * DL * DFF;
        const float* wd = Wd + (size_t)l * DFF * DL;

        rmsnorm_kernel<<<TOK, 256>>>(h, l1, x);
        gemm_kernel<4><<<dim3(DL / 64, TOK / 128), 256>>>(x, wq, nullptr, nullptr, q, TOK, DL, DL);
        gemm_kernel<4><<<dim3(DL / 64, TOK / 128), 256>>>(x, wk, nullptr, nullptr, k, TOK, DL, DL);
        gemm_kernel<4><<<dim3(DL / 64, TOK / 128), 256>>>(x, wv, nullptr, nullptr, v, TOK, DL, DL);
        rope_kernel<<<B_ * NH * SEQ, 128>>>(q, k);
        attention_kernel<<<dim3(B_ * NH, SEQ / 64), 256, ATT_SMEM>>>(q, k, v, o);
        gemm_kernel<1><<<dim3(DL / 64, TOK / 128), 256>>>(o, wo, nullptr, nullptr, h, TOK, DL, DL);
        rmsnorm_kernel<<<TOK, 256>>>(h, l2, x);
        gemm_kernel<3><<<dim3(DFF / 64, TOK / 128), 256>>>(x, wg, wu, nullptr, act, TOK, DFF, DL);
        gemm_kernel<1><<<dim3(DL / 64, TOK / 128), 256>>>(act, wd, nullptr, nullptr, h, TOK, DL, DFF);
    }

    // --- head ---
    rmsnorm_kernel<<<TOK, 256>>>(h, fnw, x);
    pool_kernel<<<dim3(DL / 256, B_), 256>>>(x, pooled);
    out1_kernel<<<(B_ * DM) / 8, 256>>>(pooled, o1W, o1b, t1);
    out2_kernel<<<B_, 256>>>(t1, o2W, o2b, y);
}

// round 3
// speedup vs baseline: 2.7466x; 2.7466x over previous
#include <cuda_runtime.h>
#include <stdint.h>
#include <math.h>

#define B_   8
#define SP   128
#define ST   64
#define SV   64
#define SEQ  256
#define DM   768
#define DL   4096
#define NH   32
#define HD   128
#define DFF  11008
#define TOK   (B_*SEQ)        // 2048
#define TVTOK (B_*(ST+SV))    // 1024

// ---------------- scratch ----------------------------------------------------
__device__ float g_h  [TOK*(size_t)DL];
__device__ float g_x  [TOK*(size_t)DL];
__device__ float g_q  [TOK*(size_t)DL];
__device__ float g_k  [TOK*(size_t)DL];
__device__ float g_v  [TOK*(size_t)DL];
__device__ float g_o  [TOK*(size_t)DL];
__device__ float g_act [TOK*(size_t)DFF];
__device__ float g_act2[TOK*(size_t)DFF];
__device__ float g_tv [TVTOK*(size_t)DM];
__device__ float g_tvp[TVTOK*(size_t)DL];
__device__ float g_pooled[B_*DL];
__device__ float g_t1[B_*DM];

// ---------------- small kernels ----------------------------------------------
__global__ void gather_embed_kernel(const int* __restrict__ ids,
                                    const float* __restrict__ tab,
                                    float* __restrict__ h)
{
    int t = blockIdx.x; int b = t / SP, s = t % SP;
    int id = ids[t];
    const float4* src = (const float4*)(tab + (size_t)id * DL);
    float4* dst = (float4*)(h + ((size_t)(b*SEQ + s)) * DL);
    for (int i = threadIdx.x; i < DL/4; i += blockDim.x) dst[i] = src[i];
}

__global__ void pack_tv_kernel(const float* __restrict__ text,
                               const float* __restrict__ vis,
                               float* __restrict__ tv)
{
    int t = blockIdx.x; int b = t / SP, w = t % SP;
    const float* src = (w < ST) ? (text + ((size_t)(b*ST + w)) * DM)
                                : (vis  + ((size_t)(b*SV + (w-ST))) * DM);
    float4* dst = (float4*)(tv + (size_t)t * DM);
    const float4* s4 = (const float4*)src;
    for (int i = threadIdx.x; i < DM/4; i += blockDim.x) dst[i] = s4[i];
}

__global__ void scatter_tvp_kernel(const float* __restrict__ tvp,
                                   float* __restrict__ h)
{
    int t = blockIdx.x; int b = t / SP, w = t % SP;
    const float4* src = (const float4*)(tvp + (size_t)t * DL);
    float4* dst = (float4*)(h + ((size_t)(b*SEQ + SP + w)) * DL);
    for (int i = threadIdx.x; i < DL/4; i += blockDim.x) dst[i] = src[i];
}

__global__ void rmsnorm_kernel(const float* __restrict__ in,
                               const float* __restrict__ w,
                               float* __restrict__ out)
{
    int r = blockIdx.x;
    const float4* x4 = (const float4*)(in + (size_t)r * DL);
    float ss = 0.f;
    for (int i = threadIdx.x; i < DL/4; i += 256) {
        float4 v = x4[i];
        ss += v.x*v.x + v.y*v.y + v.z*v.z + v.w*v.w;
    }
    __shared__ float red[8];
    __shared__ float stot;
    int lane = threadIdx.x & 31, wp = threadIdx.x >> 5;
    for (int o = 16; o; o >>= 1) ss += __shfl_down_sync(0xffffffffu, ss, o);
    if (!lane) red[wp] = ss;
    __syncthreads();
    if (threadIdx.x == 0) {
        float s = 0.f;
        for (int i = 0; i < 8; i++) s += red[i];
        stot = rsqrtf(s / (float)DL + 1e-5f);
    }
    __syncthreads();
    float sc = stot;
    const float4* w4 = (const float4*)w;
    float4* o4 = (float4*)(out + (size_t)r * DL);
    for (int i = threadIdx.x; i < DL/4; i += 256) {
        float4 v = x4[i], ww = w4[i];
        v.x *= sc*ww.x; v.y *= sc*ww.y; v.z *= sc*ww.z; v.w *= sc*ww.w;
        o4[i] = v;
    }
}

// ---------------- tf32 tensor-core GEMM --------------------------------------
// C[M,N] = A[M,K] @ B[K,N], fp32 in/out, tf32 mma, fp32 accumulate.
// EPI: 0=store  1=accumulate into C  2=store+bias  4=store to [B,H,S,D]
// BM=128 BN=128 BK=32, 256 threads (8 warps, 2x4), warp tile 64x32.

__device__ __forceinline__ unsigned f2tf(float f) {
    unsigned u; asm("cvt.rna.tf32.f32 %0, %1;" : "=r"(u) : "f"(f)); return u;
}
__device__ __forceinline__ void cpa16(unsigned s, const void* g) {
    asm volatile("cp.async.cg.shared.global [%0], [%1], 16;" :: "r"(s), "l"(g));
}
__device__ __forceinline__ void cpa_commit() {
    asm volatile("cp.async.commit_group;");
}
__device__ __forceinline__ void cpa_wait0() {
    asm volatile("cp.async.wait_group 0;");
}
__device__ __forceinline__ void mma8(float4& d, const unsigned a[4], const unsigned b[2]) {
    asm volatile(
        "mma.sync.aligned.m16n8k8.row.col.f32.tf32.tf32.f32 "
        "{%0,%1,%2,%3}, {%4,%5,%6,%7}, {%8,%9}, {%0,%1,%2,%3};"
        : "+f"(d.x), "+f"(d.y), "+f"(d.z), "+f"(d.w)
        : "r"(a[0]), "r"(a[1]), "r"(a[2]), "r"(a[3]), "r"(b[0]), "r"(b[1]));
}

#define AS_STRIDE 36
#define BS_STRIDE 136
#define BUF_FLOATS (128*AS_STRIDE + 32*BS_STRIDE)   // 4608 + 4352 = 8960
#define GEMM_SMEM  (2 * BUF_FLOATS * 4)             // 71680 bytes

template <int EPI>
__global__ void __launch_bounds__(256, 2)
gemm_tc(const float* __restrict__ A, const float* __restrict__ B,
        const float* __restrict__ bias, float* __restrict__ C,
        int M, int N, int K)
{
    extern __shared__ float sm[];
    const int tid = threadIdx.x;
    const int bm = blockIdx.y * 128, bn = blockIdx.x * 128;
    const int w = tid >> 5, lane = tid & 31;
    const int wm = w >> 2, wn = w & 3;
    const int g = lane >> 2, tig = lane & 3;

    float4 acc[4][4];
    #pragma unroll
    for (int i = 0; i < 4; i++)
        #pragma unroll
        for (int j = 0; j < 4; j++) acc[i][j] = make_float4(0.f, 0.f, 0.f, 0.f);

    const int ar = tid >> 3, ac = (tid & 7) * 4;   // A loader: rows ar+32i, cols ac..ac+3
    const int kr = tid >> 5, nc = (tid & 31) * 4;  // B loader: rows kr+8i,  cols nc..nc+3

    const int KT = K / 32;
    int buf = 0;

    // prefetch tile 0
    {
        float* as = sm; float* bs = sm + 128 * AS_STRIDE;
        #pragma unroll
        for (int i = 0; i < 4; i++)
            cpa16((unsigned)__cvta_generic_to_shared(as + (ar + i*32) * AS_STRIDE + ac),
                  A + (size_t)(bm + ar + i*32) * K + ac);
        #pragma unroll
        for (int i = 0; i < 4; i++)
            cpa16((unsigned)__cvta_generic_to_shared(bs + (kr + i*8) * BS_STRIDE + nc),
                  B + (size_t)(kr + i*8) * N + (bn + nc));
        cpa_commit();
    }

    for (int kt = 0; kt < KT; kt++) {
        cpa_wait0();
        __syncthreads();
        if (kt + 1 < KT) {
            int k0 = (kt + 1) * 32;
            float* as = sm + (buf ^ 1) * BUF_FLOATS;
            float* bs = as + 128 * AS_STRIDE;
            #pragma unroll
            for (int i = 0; i < 4; i++)
                cpa16((unsigned)__cvta_generic_to_shared(as + (ar + i*32) * AS_STRIDE + ac),
                      A + (size_t)(bm + ar + i*32) * K + (k0 + ac));
            #pragma unroll
            for (int i = 0; i < 4; i++)
                cpa16((unsigned)__cvta_generic_to_shared(bs + (kr + i*8) * BS_STRIDE + nc),
                      B + (size_t)(k0 + kr + i*8) * N + (bn + nc));
            cpa_commit();
        }

        const float* as = sm + buf * BUF_FLOATS;
        const float* bs = as + 128 * AS_STRIDE;

        #pragma unroll
        for (int k8 = 0; k8 < 4; k8++) {
            unsigned af[4][4], bf[4][2];
            #pragma unroll
            for (int mi = 0; mi < 4; mi++) {
                const float* base = as + (wm*64 + mi*16) * AS_STRIDE + k8*8;
                af[mi][0] = f2tf(base[(g    ) * AS_STRIDE + tig    ]);
                af[mi][1] = f2tf(base[(g + 8) * AS_STRIDE + tig    ]);
                af[mi][2] = f2tf(base[(g    ) * AS_STRIDE + tig + 4]);
                af[mi][3] = f2tf(base[(g + 8) * AS_STRIDE + tig + 4]);
            }
            #pragma unroll
            for (int ni = 0; ni < 4; ni++) {
                const float* base = bs + (k8*8) * BS_STRIDE + wn*32 + ni*8 + g;
                bf[ni][0] = f2tf(base[ tig      * BS_STRIDE]);
                bf[ni][1] = f2tf(base[(tig + 4) * BS_STRIDE]);
            }
            #pragma unroll
            for (int mi = 0; mi < 4; mi++)
                #pragma unroll
                for (int ni = 0; ni < 4; ni++)
                    mma8(acc[mi][ni], af[mi], bf[ni]);
        }
        buf ^= 1;
    }

    // epilogue
    #pragma unroll
    for (int mi = 0; mi < 4; mi++) {
        #pragma unroll
        for (int ni = 0; ni < 4; ni++) {
            int m = bm + wm*64 + mi*16 + g;
            int n = bn + wn*32 + ni*8 + 2*tig;
            float2 lo = make_float2(acc[mi][ni].x, acc[mi][ni].y); // row m
            float2 hi = make_float2(acc[mi][ni].z, acc[mi][ni].w); // row m+8
            if constexpr (EPI == 0) {
                *(float2*)&C[(size_t)m * N + n]       = lo;
                *(float2*)&C[(size_t)(m+8) * N + n]   = hi;
            } else if constexpr (EPI == 1) {
                float2 c0 = *(float2*)&C[(size_t)m * N + n];
                float2 c1 = *(float2*)&C[(size_t)(m+8) * N + n];
                c0.x += lo.x; c0.y += lo.y; c1.x += hi.x; c1.y += hi.y;
                *(float2*)&C[(size_t)m * N + n]     = c0;
                *(float2*)&C[(size_t)(m+8) * N + n] = c1;
            } else if constexpr (EPI == 2) {
                float2 b2 = *(const float2*)&bias[n];
                lo.x += b2.x; lo.y += b2.y; hi.x += b2.x; hi.y += b2.y;
                *(float2*)&C[(size_t)m * N + n]     = lo;
                *(float2*)&C[(size_t)(m+8) * N + n] = hi;
            } else { // EPI == 4 : scatter to [B,H,S,D]
                int hh = n >> 7, d = n & 127;
                {
                    int b = m >> 8, s = m & 255;
                    *(float2*)&C[(((size_t)(b*NH + hh)) * SEQ + s) * HD + d] = lo;
                }
                {
                    int m2 = m + 8;
                    int b = m2 >> 8, s = m2 & 255;
                    *(float2*)&C[(((size_t)(b*NH + hh)) * SEQ + s) * HD + d] = hi;
                }
            }
        }
    }
}

// ---------------- silu(gate) * up --------------------------------------------
__global__ void silu_mul_kernel(const float* __restrict__ gte,
                                const float* __restrict__ up,
                                float* __restrict__ out, int n4)
{
    int i = blockIdx.x * 256 + threadIdx.x;
    if (i >= n4) return;
    float4 gv = ((const float4*)gte)[i];
    float4 uv = ((const float4*)up)[i];
    float4 r;
    r.x = gv.x / (1.f + __expf(-gv.x)) * uv.x;
    r.y = gv.y / (1.f + __expf(-gv.y)) * uv.y;
    r.z = gv.z / (1.f + __expf(-gv.z)) * uv.z;
    r.w = gv.w / (1.f + __expf(-gv.w)) * uv.w;
    ((float4*)out)[i] = r;
}

// ---------------- RoPE --------------------------------------------------------
__global__ void rope_kernel(float* __restrict__ q, float* __restrict__ k)
{
    int idx = blockIdx.x;            // (b*NH + h)*SEQ + s
    int s = idx & (SEQ - 1);
    int tid = threadIdx.x;           // 128: 0-63 -> q, 64-127 -> k
    float* p = (tid < 64 ? q : k) + (size_t)idx * HD;
    int d = tid & 63;
    float inv = expf(-9.210340371976184f * (float)(2 * d) * (1.0f / 128.0f));
    float ang = (float)s * inv;
    float sn, c;
    sincosf(ang, &sn, &c);
    float x1 = p[d], x2 = p[d + 64];
    p[d]      = x1 * c - x2 * sn;
    p[d + 64] = x2 * c + x1 * sn;
}

// ---------------- fused causal attention -------------------------------------
#define ATT_SMEM ((64*132 + 8704 + 64*260) * 4)

__global__ void __launch_bounds__(256)
attention_kernel(const float* __restrict__ Q, const float* __restrict__ K,
                 const float* __restrict__ V, float* __restrict__ O)
{
    extern __shared__ float smatt[];
    float* qs = smatt;
    float* kv = smatt + 64 * 132;
    float* sc = kv + 8704;

    int bh = blockIdx.x, qt = blockIdx.y;
    const float* Qb = Q + ((size_t)bh * SEQ + qt * 64) * HD;
    const float* Kb = K + (size_t)bh * SEQ * HD;
    const float* Vb = V + (size_t)bh * SEQ * HD;
    int tid = threadIdx.x;

    for (int s2 = tid; s2 < 64 * 32; s2 += 256) {
        int r = s2 >> 5, c = (s2 & 31) * 4;
        float4 v = *(const float4*)(Qb + r * HD + c);
        float* qr = qs + r * 132 + c;
        qr[0] = v.x; qr[1] = v.y; qr[2] = v.z; qr[3] = v.w;
    }

    int ty = tid >> 4, tx = tid & 15;
    const float scale = 0.08838834764831845f;

    for (int kt = 0; kt <= qt; kt++) {
        __syncthreads();
        for (int s2 = tid; s2 < 64 * 32; s2 += 256) {
            int r = s2 >> 5, c = (s2 & 31) * 4;
            float4 v = *(const float4*)(Kb + (kt * 64 + r) * HD + c);
            kv[(c + 0) * 68 + r] = v.x; kv[(c + 1) * 68 + r] = v.y;
            kv[(c + 2) * 68 + r] = v.z; kv[(c + 3) * 68 + r] = v.w;
        }
        __syncthreads();

        float acc[4][4] = {};
        #pragma unroll 4
        for (int d = 0; d < HD; d++) {
            float a0 = qs[(ty * 4 + 0) * 132 + d];
            float a1 = qs[(ty * 4 + 1) * 132 + d];
            float a2 = qs[(ty * 4 + 2) * 132 + d];
            float a3 = qs[(ty * 4 + 3) * 132 + d];
            float4 bv = *(const float4*)&kv[d * 68 + tx * 4];
            acc[0][0] += a0*bv.x; acc[0][1] += a0*bv.y; acc[0][2] += a0*bv.z; acc[0][3] += a0*bv.w;
            acc[1][0] += a1*bv.x; acc[1][1] += a1*bv.y; acc[1][2] += a1*bv.z; acc[1][3] += a1*bv.w;
            acc[2][0] += a2*bv.x; acc[2][1] += a2*bv.y; acc[2][2] += a2*bv.z; acc[2][3] += a2*bv.w;
            acc[3][0] += a3*bv.x; acc[3][1] += a3*bv.y; acc[3][2] += a3*bv.z; acc[3][3] += a3*bv.w;
        }

        int qg0 = qt * 64;
        #pragma unroll
        for (int i = 0; i < 4; i++) {
            int qi = ty * 4 + i; int qg = qg0 + qi;
            #pragma unroll
            for (int j = 0; j < 4; j++) {
                int kg = kt * 64 + tx * 4 + j;
                sc[qi * 260 + kg] = (kg <= qg) ? acc[i][j] * scale : -1e30f;
            }
        }
    }
    __syncthreads();

    int row = tid >> 2, l4 = tid & 3;
    int nk = (qt + 1) * 64;
    float mx = -1e30f;
    for (int j = l4; j < nk; j += 4) mx = fmaxf(mx, sc[row * 260 + j]);
    mx = fmaxf(mx, __shfl_xor_sync(0xffffffffu, mx, 1));
    mx = fmaxf(mx, __shfl_xor_sync(0xffffffffu, mx, 2));
    float sum = 0.f;
    for (int j = l4; j < nk; j += 4) {
        float e = __expf(sc[row * 260 + j] - mx);
        sc[row * 260 + j] = e; sum += e;
    }
    sum += __shfl_xor_sync(0xffffffffu, sum, 1);
    sum += __shfl_xor_sync(0xffffffffu, sum, 2);
    float invs = 1.f / sum;
    for (int j = l4; j < nk; j += 4) sc[row * 260 + j] *= invs;
    __syncthreads();

    float out[4][8] = {};
    for (int kt = 0; kt <= qt; kt++) {
        for (int s2 = tid; s2 < 64 * 32; s2 += 256) {
            int r = s2 >> 5, c = (s2 & 31) * 4;
            float4 v = *(const float4*)(Vb + (kt * 64 + r) * HD + c);
            *(float4*)&kv[r * 132 + c] = v;
        }
        __syncthreads();
        for (int j = 0; j < 64; j++) {
            float p0 = sc[(ty * 4 + 0) * 260 + kt * 64 + j];
            float p1 = sc[(ty * 4 + 1) * 260 + kt * 64 + j];
            float p2 = sc[(ty * 4 + 2) * 260 + kt * 64 + j];
            float p3 = sc[(ty * 4 + 3) * 260 + kt * 64 + j];
            float4 v0 = *(const float4*)&kv[j * 132 + tx * 8];
            float4 v1 = *(const float4*)&kv[j * 132 + tx * 8 + 4];
            out[0][0]+=p0*v0.x; out[0][1]+=p0*v0.y; out[0][2]+=p0*v0.z; out[0][3]+=p0*v0.w;
            out[0][4]+=p0*v1.x; out[0][5]+=p0*v1.y; out[0][6]+=p0*v1.z; out[0][7]+=p0*v1.w;
            out[1][0]+=p1*v0.x; out[1][1]+=p1*v0.y; out[1][2]+=p1*v0.z; out[1][3]+=p1*v0.w;
            out[1][4]+=p1*v1.x; out[1][5]+=p1*v1.y; out[1][6]+=p1*v1.z; out[1][7]+=p1*v1.w;
            out[2][0]+=p2*v0.x; out[2][1]+=p2*v0.y; out[2][2]+=p2*v0.z; out[2][3]+=p2*v0.w;
            out[2][4]+=p2*v1.x; out[2][5]+=p2*v1.y; out[2][6]+=p2*v1.z; out[2][7]+=p2*v1.w;
            out[3][0]+=p3*v0.x; out[3][1]+=p3*v0.y; out[3][2]+=p3*v0.z; out[3][3]+=p3*v0.w;
            out[3][4]+=p3*v1.x; out[3][5]+=p3*v1.y; out[3][6]+=p3*v1.z; out[3][7]+=p3*v1.w;
        }
        __syncthreads();
    }

    int b = bh >> 5, hh = bh & 31;
    #pragma unroll
    for (int a = 0; a < 4; a++) {
        int tokrow = qt * 64 + ty * 4 + a;
        float* dst = O + ((size_t)(b * SEQ + tokrow)) * DL + hh * HD + tx * 8;
        *(float4*)dst       = make_float4(out[a][0], out[a][1], out[a][2], out[a][3]);
        *(float4*)(dst + 4) = make_float4(out[a][4], out[a][5], out[a][6], out[a][7]);
    }
}

// ---------------- pooling + output head --------------------------------------
__global__ void pool_kernel(const float* __restrict__ x, float* __restrict__ pooled)
{
    int b = blockIdx.y;
    int d = blockIdx.x * 256 + threadIdx.x;
    const float* p = x + (size_t)b * SEQ * DL + d;
    float s = 0.f;
    for (int t = 0; t < SEQ; t++) s += p[(size_t)t * DL];
    pooled[b * DL + d] = s * (1.0f / SEQ);
}

__global__ void out1_kernel(const float* __restrict__ pooled, const float* __restrict__ W,
                            const float* __restrict__ b1, float* __restrict__ t1)
{
    int o = blockIdx.x * 8 + (threadIdx.x >> 5);
    int lane = threadIdx.x & 31;
    int b = o / DM, j = o % DM;
    const float* p = pooled + (size_t)b * DL;
    float s = 0.f;
    for (int i = lane; i < DL; i += 32) s += p[i] * W[(size_t)i * DM + j];
    for (int off = 16; off; off >>= 1) s += __shfl_down_sync(0xffffffffu, s, off);
    if (!lane) t1[o] = s + b1[j];
}

__global__ void out2_kernel(const float* __restrict__ t1, const float* __restrict__ W2,
                            const float* __restrict__ b2, float* __restrict__ y)
{
    int b = blockIdx.x;
    float s = 0.f;
    for (int j = threadIdx.x; j < DM; j += 256) s += t1[b * DM + j] * W2[j];
    __shared__ float red[8];
    int lane = threadIdx.x & 31, wp = threadIdx.x >> 5;
    for (int o = 16; o; o >>= 1) s += __shfl_down_sync(0xffffffffu, s, o);
    if (!lane) red[wp] = s;
    __syncthreads();
    if (threadIdx.x == 0) {
        float t = 0.f;
        for (int i = 0; i < 8; i++) t += red[i];
        y[b] = t + b2[0];
    }
}

// ---------------- host orchestration -----------------------------------------
extern "C" void kernel_launch(void* const* d_in, const int* in_sizes, int n_in,
                              void* d_out, int out_size)
{
    const float* text = (const float*)d_in[0];
    const float* vis  = (const float*)d_in[1];
    const int*   ids  = (const int*)  d_in[2];
    const float* inW  = (const float*)d_in[3];
    const float* inb  = (const float*)d_in[4];
    const float* etab = (const float*)d_in[5];
    const float* Wq   = (const float*)d_in[6];
    const float* Wk   = (const float*)d_in[7];
    const float* Wv   = (const float*)d_in[8];
    const float* Wo   = (const float*)d_in[9];
    const float* ln1  = (const float*)d_in[10];
    const float* ln2  = (const float*)d_in[11];
    const float* Wg   = (const float*)d_in[12];
    const float* Wu   = (const float*)d_in[13];
    const float* Wd   = (const float*)d_in[14];
    const float* fnw  = (const float*)d_in[15];
    const float* o1W  = (const float*)d_in[16];
    const float* o1b  = (const float*)d_in[17];
    const float* o2W  = (const float*)d_in[18];
    const float* o2b  = (const float*)d_in[19];
    float* y = (float*)d_out;

    float *h, *x, *q, *k, *v, *o, *act, *act2, *tv, *tvp, *pooled, *t1;
    cudaGetSymbolAddress((void**)&h,      g_h);
    cudaGetSymbolAddress((void**)&x,      g_x);
    cudaGetSymbolAddress((void**)&q,      g_q);
    cudaGetSymbolAddress((void**)&k,      g_k);
    cudaGetSymbolAddress((void**)&v,      g_v);
    cudaGetSymbolAddress((void**)&o,      g_o);
    cudaGetSymbolAddress((void**)&act,    g_act);
    cudaGetSymbolAddress((void**)&act2,   g_act2);
    cudaGetSymbolAddress((void**)&tv,     g_tv);
    cudaGetSymbolAddress((void**)&tvp,    g_tvp);
    cudaGetSymbolAddress((void**)&pooled, g_pooled);
    cudaGetSymbolAddress((void**)&t1,     g_t1);

    cudaFuncSetAttribute(attention_kernel,
                         cudaFuncAttributeMaxDynamicSharedMemorySize, ATT_SMEM);
    cudaFuncSetAttribute(gemm_tc<0>, cudaFuncAttributeMaxDynamicSharedMemorySize, GEMM_SMEM);
    cudaFuncSetAttribute(gemm_tc<1>, cudaFuncAttributeMaxDynamicSharedMemorySize, GEMM_SMEM);
    cudaFuncSetAttribute(gemm_tc<2>, cudaFuncAttributeMaxDynamicSharedMemorySize, GEMM_SMEM);
    cudaFuncSetAttribute(gemm_tc<4>, cudaFuncAttributeMaxDynamicSharedMemorySize, GEMM_SMEM);

    // --- embeddings ---
    gather_embed_kernel<<<B_ * SP, 256>>>(ids, etab, h);
    pack_tv_kernel<<<TVTOK, 256>>>(text, vis, tv);
    gemm_tc<2><<<dim3(DL/128, TVTOK/128), 256, GEMM_SMEM>>>(tv, inW, inb, tvp, TVTOK, DL, DM);
    scatter_tvp_kernel<<<TVTOK, 256>>>(tvp, h);

    // --- transformer layers ---
    for (int l = 0; l < 2; l++) {
        const float* wq = Wq + (size_t)l * DL * DL;
        const float* wk = Wk + (size_t)l * DL * DL;
        const float* wv = Wv + (size_t)l * DL * DL;
        const float* wo = Wo + (size_t)l * DL * DL;
        const float* l1 = ln1 + (size_t)l * DL;
        const float* l2 = ln2 + (size_t)l * DL;
        const float* wg = Wg + (size_t)l * DL * DFF;
        const float* wu = Wu + (size_t)l * DL * DFF;
        const float* wd = Wd + (size_t)l * DFF * DL;

        rmsnorm_kernel<<<TOK, 256>>>(h, l1, x);
        gemm_tc<4><<<dim3(DL/128, TOK/128), 256, GEMM_SMEM>>>(x, wq, nullptr, q, TOK, DL, DL);
        gemm_tc<4><<<dim3(DL/128, TOK/128), 256, GEMM_SMEM>>>(x, wk, nullptr, k, TOK, DL, DL);
        gemm_tc<4><<<dim3(DL/128, TOK/128), 256, GEMM_SMEM>>>(x, wv, nullptr, v, TOK, DL, DL);
        rope_kernel<<<B_ * NH * SEQ, 128>>>(q, k);
        attention_kernel<<<dim3(B_ * NH, SEQ/64), 256, ATT_SMEM>>>(q, k, v, o);
        gemm_tc<1><<<dim3(DL/128, TOK/128), 256, GEMM_SMEM>>>(o, wo, nullptr, h, TOK, DL, DL);
        rmsnorm_kernel<<<TOK, 256>>>(h, l2, x);
        gemm_tc<0><<<dim3(DFF/128, TOK/128), 256, GEMM_SMEM>>>(x, wg, nullptr, act,  TOK, DFF, DL);
        gemm_tc<0><<<dim3(DFF/128, TOK/128), 256, GEMM_SMEM>>>(x, wu, nullptr, act2, TOK, DFF, DL);
        silu_mul_kernel<<<(TOK*DFF/4 + 255)/256, 256>>>(act, act2, act, TOK*DFF/4);
        gemm_tc<1><<<dim3(DL/128, TOK/128), 256, GEMM_SMEM>>>(act, wd, nullptr, h, TOK, DL, DFF);
    }

    // --- head ---
    rmsnorm_kernel<<<TOK, 256>>>(h, fnw, x);
    pool_kernel<<<dim3(DL/256, B_), 256>>>(x, pooled);
    out1_kernel<<<(B_ * DM) / 8, 256>>>(pooled, o1W, o1b, t1);
    out2_kernel<<<B_, 256>>>(t1, o2W, o2b, y);
}

// round 12
// speedup vs baseline: 5.4541x; 1.9857x over previous
#include <cuda_runtime.h>
#include <cuda_fp16.h>
#include <stdint.h>
#include <math.h>

#define B_   8
#define SP   128
#define ST   64
#define SV   64
#define SEQ  256
#define DM   768
#define DL   4096
#define NH   32
#define HD   128
#define DFF  11008
#define TOK   (B_*SEQ)        // 2048
#define TVTOK (B_*(ST+SV))    // 1024

// ---------------- scratch ----------------------------------------------------
__device__ float g_h  [TOK*(size_t)DL];
__device__ float g_x  [TOK*(size_t)DL];          // final-norm f32 out
__device__ float g_q  [TOK*(size_t)DL];
__device__ float g_k  [TOK*(size_t)DL];
__device__ float g_v  [TOK*(size_t)DL];
__device__ float g_act [TOK*(size_t)DFF];
__device__ float g_act2[TOK*(size_t)DFF];
__device__ float g_tvp[TVTOK*(size_t)DL];
__device__ float g_pooled[B_*DL];
__device__ float g_t1[B_*DM];

// fp16 activations
__device__ __half g_xh  [TOK*(size_t)DL];
__device__ __half g_oh  [TOK*(size_t)DL];
__device__ __half g_acth[TOK*(size_t)DFF];
__device__ __half g_tvh [TVTOK*(size_t)DM];

// fp16 weights
__device__ __half g_inWh[(size_t)DM*DL];
__device__ __half g_wqh [2*(size_t)DL*DL];
__device__ __half g_wkh [2*(size_t)DL*DL];
__device__ __half g_wvh [2*(size_t)DL*DL];
__device__ __half g_woh [2*(size_t)DL*DL];
__device__ __half g_wgh [2*(size_t)DL*DFF];
__device__ __half g_wuh [2*(size_t)DL*DFF];
__device__ __half g_wdh [2*(size_t)DFF*DL];

__device__ __forceinline__ unsigned pack_h2(float a, float b) {
    __half2 h = __floats2half2_rn(a, b);
    return *reinterpret_cast<unsigned*>(&h);
}

// ---------------- f32 -> fp16 conversion -------------------------------------
__global__ void f2h_kernel(const float* __restrict__ in, __half* __restrict__ out, long n4)
{
    long stride = (long)gridDim.x * blockDim.x;
    for (long i = (long)blockIdx.x * blockDim.x + threadIdx.x; i < n4; i += stride) {
        float4 v = ((const float4*)in)[i];
        uint2 r;
        r.x = pack_h2(v.x, v.y);
        r.y = pack_h2(v.z, v.w);
        ((uint2*)out)[i] = r;
    }
}

// ---------------- embedding / pack / scatter ---------------------------------
__global__ void gather_embed_kernel(const int* __restrict__ ids,
                                    const float* __restrict__ tab,
                                    float* __restrict__ h)
{
    int t = blockIdx.x; int b = t / SP, s = t % SP;
    int id = ids[t];
    const float4* src = (const float4*)(tab + (size_t)id * DL);
    float4* dst = (float4*)(h + ((size_t)(b*SEQ + s)) * DL);
    for (int i = threadIdx.x; i < DL/4; i += blockDim.x) dst[i] = src[i];
}

__global__ void pack_tv_kernel(const float* __restrict__ text,
                               const float* __restrict__ vis,
                               __half* __restrict__ tvh)
{
    int t = blockIdx.x; int b = t / SP, w = t % SP;
    const float* src = (w < ST) ? (text + ((size_t)(b*ST + w)) * DM)
                                : (vis  + ((size_t)(b*SV + (w-ST))) * DM);
    const float4* s4 = (const float4*)src;
    uint2* dst = (uint2*)(tvh + (size_t)t * DM);
    for (int i = threadIdx.x; i < DM/4; i += blockDim.x) {
        float4 v = s4[i];
        uint2 r; r.x = pack_h2(v.x, v.y); r.y = pack_h2(v.z, v.w);
        dst[i] = r;
    }
}

__global__ void scatter_tvp_kernel(const float* __restrict__ tvp,
                                   float* __restrict__ h)
{
    int t = blockIdx.x; int b = t / SP, w = t % SP;
    const float4* src = (const float4*)(tvp + (size_t)t * DL);
    float4* dst = (float4*)(h + ((size_t)(b*SEQ + SP + w)) * DL);
    for (int i = threadIdx.x; i < DL/4; i += blockDim.x) dst[i] = src[i];
}

// ---------------- rmsnorm (f32 out and fp16 out variants) --------------------
template <int HALF_OUT>
__global__ void rmsnorm_kernel(const float* __restrict__ in,
                               const float* __restrict__ w,
                               float* __restrict__ outf,
                               __half* __restrict__ outh)
{
    int r = blockIdx.x;
    const float4* x4 = (const float4*)(in + (size_t)r * DL);
    float ss = 0.f;
    for (int i = threadIdx.x; i < DL/4; i += 256) {
        float4 v = x4[i];
        ss += v.x*v.x + v.y*v.y + v.z*v.z + v.w*v.w;
    }
    __shared__ float red[8];
    __shared__ float stot;
    int lane = threadIdx.x & 31, wp = threadIdx.x >> 5;
    for (int o = 16; o; o >>= 1) ss += __shfl_down_sync(0xffffffffu, ss, o);
    if (!lane) red[wp] = ss;
    __syncthreads();
    if (threadIdx.x == 0) {
        float s = 0.f;
        for (int i = 0; i < 8; i++) s += red[i];
        stot = rsqrtf(s / (float)DL + 1e-5f);
    }
    __syncthreads();
    float sc = stot;
    const float4* w4 = (const float4*)w;
    for (int i = threadIdx.x; i < DL/4; i += 256) {
        float4 v = x4[i], ww = w4[i];
        v.x *= sc*ww.x; v.y *= sc*ww.y; v.z *= sc*ww.z; v.w *= sc*ww.w;
        if (HALF_OUT) {
            uint2 rr; rr.x = pack_h2(v.x, v.y); rr.y = pack_h2(v.z, v.w);
            ((uint2*)(outh + (size_t)r * DL))[i] = rr;
        } else {
            ((float4*)(outf + (size_t)r * DL))[i] = v;
        }
    }
}

// ---------------- fp16 tensor-core GEMM --------------------------------------
// C[M,N] = A[M,K] @ B[K,N], fp16 in, fp32 accumulate / out.
// EPI: 0=store  1=accumulate into C  2=store+bias  4=scatter to [B,H,S,D]
// BM=128 BN=128 BK=32, 256 threads (8 warps, 2x4), warp tile 64x32, 3-stage cp.async.

__device__ __forceinline__ void cpa16(unsigned s, const void* g) {
    asm volatile("cp.async.cg.shared.global [%0], [%1], 16;" :: "r"(s), "l"(g));
}
__device__ __forceinline__ void cpa_commit() {
    asm volatile("cp.async.commit_group;");
}
__device__ __forceinline__ void cpa_wait1() {
    asm volatile("cp.async.wait_group 1;");
}
__device__ __forceinline__ void ldmx4(unsigned a[4], unsigned addr) {
    asm volatile("ldmatrix.sync.aligned.m8n8.x4.shared.b16 {%0,%1,%2,%3}, [%4];"
                 : "=r"(a[0]), "=r"(a[1]), "=r"(a[2]), "=r"(a[3]) : "r"(addr));
}
__device__ __forceinline__ void ldmx2t(unsigned b[2], unsigned addr) {
    asm volatile("ldmatrix.sync.aligned.m8n8.x2.trans.shared.b16 {%0,%1}, [%2];"
                 : "=r"(b[0]), "=r"(b[1]) : "r"(addr));
}
__device__ __forceinline__ void mma16(float4& d, const unsigned a[4], const unsigned b[2]) {
    asm volatile(
        "mma.sync.aligned.m16n8k16.row.col.f32.f16.f16.f32 "
        "{%0,%1,%2,%3}, {%4,%5,%6,%7}, {%8,%9}, {%0,%1,%2,%3};"
        : "+f"(d.x), "+f"(d.y), "+f"(d.z), "+f"(d.w)
        : "r"(a[0]), "r"(a[1]), "r"(a[2]), "r"(a[3]), "r"(b[0]), "r"(b[1]));
}

#define AS_H 40                       // A smem row stride (halfs)
#define BS_H 136                      // B smem row stride (halfs)
#define STG_H (128*AS_H + 32*BS_H)    // 9472 halfs per stage
#define GEMM_SMEM (3 * STG_H * 2)     // 56832 bytes

template <int EPI>
__global__ void __launch_bounds__(256, 2)
gemm_h(const __half* __restrict__ A, const __half* __restrict__ B,
       const float* __restrict__ bias, float* __restrict__ C,
       int M, int N, int K)
{
    extern __shared__ __half smh[];
    const unsigned smb = (unsigned)__cvta_generic_to_shared(smh);
    const int tid = threadIdx.x;
    const int bm = blockIdx.y * 128, bn = blockIdx.x * 128;
    const int w = tid >> 5, lane = tid & 31;
    const int wm = w >> 2, wn = w & 3;
    const int g = lane >> 2, tig = lane & 3;
    const int l16 = lane & 15, lhi = lane >> 4;

    float4 acc[4][4];
    #pragma unroll
    for (int i = 0; i < 4; i++)
        #pragma unroll
        for (int j = 0; j < 4; j++) acc[i][j] = make_float4(0.f, 0.f, 0.f, 0.f);

    const int KT = K / 32;

    // ---- tile loader ----
    auto load_tile = [&](int stage, int k0) {
        unsigned as = smb + stage * (STG_H * 2);
        unsigned bs = as + 128 * AS_H * 2;
        #pragma unroll
        for (int q = 0; q < 2; q++) {
            int idx = tid + q * 256;
            int r = idx >> 2, c = idx & 3;
            cpa16(as + (r * AS_H + c * 8) * 2,
                  A + (size_t)(bm + r) * K + k0 + c * 8);
        }
        #pragma unroll
        for (int q = 0; q < 2; q++) {
            int idx = tid + q * 256;
            int r = idx >> 4, c = idx & 15;
            cpa16(bs + (r * BS_H + c * 8) * 2,
                  B + (size_t)(k0 + r) * N + bn + c * 8);
        }
    };

    load_tile(0, 0);  cpa_commit();
    load_tile(1, 32); cpa_commit();

    int buf = 0;
    for (int kt = 0; kt < KT; kt++) {
        cpa_wait1();
        __syncthreads();
        if (kt + 2 < KT) load_tile((kt + 2) % 3, (kt + 2) * 32);
        cpa_commit();

        unsigned as = smb + buf * (STG_H * 2);
        unsigned bs = as + 128 * AS_H * 2;

        #pragma unroll
        for (int kk = 0; kk < 2; kk++) {
            unsigned af[4][4], bf[4][2];
            #pragma unroll
            for (int mi = 0; mi < 4; mi++)
                ldmx4(af[mi], as + ((wm*64 + mi*16 + l16) * AS_H + kk*16 + lhi*8) * 2);
            #pragma unroll
            for (int ni = 0; ni < 4; ni++)
                ldmx2t(bf[ni], bs + ((kk*16 + l16) * BS_H + wn*32 + ni*8) * 2);
            #pragma unroll
            for (int mi = 0; mi < 4; mi++)
                #pragma unroll
                for (int ni = 0; ni < 4; ni++)
                    mma16(acc[mi][ni], af[mi], bf[ni]);
        }
        buf = (buf + 1) % 3;
    }

    // ---- epilogue ----
    #pragma unroll
    for (int mi = 0; mi < 4; mi++) {
        #pragma unroll
        for (int ni = 0; ni < 4; ni++) {
            int m = bm + wm*64 + mi*16 + g;
            int n = bn + wn*32 + ni*8 + 2*tig;
            float2 lo = make_float2(acc[mi][ni].x, acc[mi][ni].y); // row m
            float2 hi = make_float2(acc[mi][ni].z, acc[mi][ni].w); // row m+8
            if constexpr (EPI == 0) {
                *(float2*)&C[(size_t)m * N + n]     = lo;
                *(float2*)&C[(size_t)(m+8) * N + n] = hi;
            } else if constexpr (EPI == 1) {
                float2 c0 = *(float2*)&C[(size_t)m * N + n];
                float2 c1 = *(float2*)&C[(size_t)(m+8) * N + n];
                c0.x += lo.x; c0.y += lo.y; c1.x += hi.x; c1.y += hi.y;
                *(float2*)&C[(size_t)m * N + n]     = c0;
                *(float2*)&C[(size_t)(m+8) * N + n] = c1;
            } else if constexpr (EPI == 2) {
                float2 b2 = *(const float2*)&bias[n];
                lo.x += b2.x; lo.y += b2.y; hi.x += b2.x; hi.y += b2.y;
                *(float2*)&C[(size_t)m * N + n]     = lo;
                *(float2*)&C[(size_t)(m+8) * N + n] = hi;
            } else { // EPI == 4 : scatter to [B,H,S,D]
                int hh = n >> 7, d = n & 127;
                {
                    int b = m >> 8, s = m & 255;
                    *(float2*)&C[(((size_t)(b*NH + hh)) * SEQ + s) * HD + d] = lo;
                }
                {
                    int m2 = m + 8;
                    int b = m2 >> 8, s = m2 & 255;
                    *(float2*)&C[(((size_t)(b*NH + hh)) * SEQ + s) * HD + d] = hi;
                }
            }
        }
    }
}

// ---------------- silu(gate) * up -> fp16 ------------------------------------
__global__ void silu_mul_kernel(const float* __restrict__ gte,
                                const float* __restrict__ up,
                                __half* __restrict__ outh, int n4)
{
    int i = blockIdx.x * 256 + threadIdx.x;
    if (i >= n4) return;
    float4 gv = ((const float4*)gte)[i];
    float4 uv = ((const float4*)up)[i];
    float r0 = gv.x / (1.f + __expf(-gv.x)) * uv.x;
    float r1 = gv.y / (1.f + __expf(-gv.y)) * uv.y;
    float r2 = gv.z / (1.f + __expf(-gv.z)) * uv.z;
    float r3 = gv.w / (1.f + __expf(-gv.w)) * uv.w;
    uint2 r; r.x = pack_h2(r0, r1); r.y = pack_h2(r2, r3);
    ((uint2*)outh)[i] = r;
}

// ---------------- RoPE --------------------------------------------------------
__global__ void rope_kernel(float* __restrict__ q, float* __restrict__ k)
{
    int idx = blockIdx.x;            // (b*NH + h)*SEQ + s
    int s = idx & (SEQ - 1);
    int tid = threadIdx.x;           // 128: 0-63 -> q, 64-127 -> k
    float* p = (tid < 64 ? q : k) + (size_t)idx * HD;
    int d = tid & 63;
    float inv = expf(-9.210340371976184f * (float)(2 * d) * (1.0f / 128.0f));
    float ang = (float)s * inv;
    float sn, c;
    sincosf(ang, &sn, &c);
    float x1 = p[d], x2 = p[d + 64];
    p[d]      = x1 * c - x2 * sn;
    p[d + 64] = x2 * c + x1 * sn;
}

// ---------------- fused causal attention (fp16 output) -----------------------
#define ATT_SMEM ((64*132 + 8704 + 64*260) * 4)

__global__ void __launch_bounds__(256)
attention_kernel(const float* __restrict__ Q, const float* __restrict__ K,
                 const float* __restrict__ V, __half* __restrict__ Oh)
{
    extern __shared__ float smatt[];
    float* qs = smatt;
    float* kv = smatt + 64 * 132;
    float* sc = kv + 8704;

    int bh = blockIdx.x, qt = blockIdx.y;
    const float* Qb = Q + ((size_t)bh * SEQ + qt * 64) * HD;
    const float* Kb = K + (size_t)bh * SEQ * HD;
    const float* Vb = V + (size_t)bh * SEQ * HD;
    int tid = threadIdx.x;

    for (int s2 = tid; s2 < 64 * 32; s2 += 256) {
        int r = s2 >> 5, c = (s2 & 31) * 4;
        float4 v = *(const float4*)(Qb + r * HD + c);
        float* qr = qs + r * 132 + c;
        qr[0] = v.x; qr[1] = v.y; qr[2] = v.z; qr[3] = v.w;
    }

    int ty = tid >> 4, tx = tid & 15;
    const float scale = 0.08838834764831845f;

    for (int kt = 0; kt <= qt; kt++) {
        __syncthreads();
        for (int s2 = tid; s2 < 64 * 32; s2 += 256) {
            int r = s2 >> 5, c = (s2 & 31) * 4;
            float4 v = *(const float4*)(Kb + (kt * 64 + r) * HD + c);
            kv[(c + 0) * 68 + r] = v.x; kv[(c + 1) * 68 + r] = v.y;
            kv[(c + 2) * 68 + r] = v.z; kv[(c + 3) * 68 + r] = v.w;
        }
        __syncthreads();

        float acc[4][4] = {};
        #pragma unroll 4
        for (int d = 0; d < HD; d++) {
            float a0 = qs[(ty * 4 + 0) * 132 + d];
            float a1 = qs[(ty * 4 + 1) * 132 + d];
            float a2 = qs[(ty * 4 + 2) * 132 + d];
            float a3 = qs[(ty * 4 + 3) * 132 + d];
            float4 bv = *(const float4*)&kv[d * 68 + tx * 4];
            acc[0][0] += a0*bv.x; acc[0][1] += a0*bv.y; acc[0][2] += a0*bv.z; acc[0][3] += a0*bv.w;
            acc[1][0] += a1*bv.x; acc[1][1] += a1*bv.y; acc[1][2] += a1*bv.z; acc[1][3] += a1*bv.w;
            acc[2][0] += a2*bv.x; acc[2][1] += a2*bv.y; acc[2][2] += a2*bv.z; acc[2][3] += a2*bv.w;
            acc[3][0] += a3*bv.x; acc[3][1] += a3*bv.y; acc[3][2] += a3*bv.z; acc[3][3] += a3*bv.w;
        }

        int qg0 = qt * 64;
        #pragma unroll
        for (int i = 0; i < 4; i++) {
            int qi = ty * 4 + i; int qg = qg0 + qi;
            #pragma unroll
            for (int j = 0; j < 4; j++) {
                int kg = kt * 64 + tx * 4 + j;
                sc[qi * 260 + kg] = (kg <= qg) ? acc[i][j] * scale : -1e30f;
            }
        }
    }
    __syncthreads();

    int row = tid >> 2, l4 = tid & 3;
    int nk = (qt + 1) * 64;
    float mx = -1e30f;
    for (int j = l4; j < nk; j += 4) mx = fmaxf(mx, sc[row * 260 + j]);
    mx = fmaxf(mx, __shfl_xor_sync(0xffffffffu, mx, 1));
    mx = fmaxf(mx, __shfl_xor_sync(0xffffffffu, mx, 2));
    float sum = 0.f;
    for (int j = l4; j < nk; j += 4) {
        float e = __expf(sc[row * 260 + j] - mx);
        sc[row * 260 + j] = e; sum += e;
    }
    sum += __shfl_xor_sync(0xffffffffu, sum, 1);
    sum += __shfl_xor_sync(0xffffffffu, sum, 2);
    float invs = 1.f / sum;
    for (int j = l4; j < nk; j += 4) sc[row * 260 + j] *= invs;
    __syncthreads();

    float out[4][8] = {};
    for (int kt = 0; kt <= qt; kt++) {
        for (int s2 = tid; s2 < 64 * 32; s2 += 256) {
            int r = s2 >> 5, c = (s2 & 31) * 4;
            float4 v = *(const float4*)(Vb + (kt * 64 + r) * HD + c);
            *(float4*)&kv[r * 132 + c] = v;
        }
        __syncthreads();
        for (int j = 0; j < 64; j++) {
            float p0 = sc[(ty * 4 + 0) * 260 + kt * 64 + j];
            float p1 = sc[(ty * 4 + 1) * 260 + kt * 64 + j];
            float p2 = sc[(ty * 4 + 2) * 260 + kt * 64 + j];
            float p3 = sc[(ty * 4 + 3) * 260 + kt * 64 + j];
            float4 v0 = *(const float4*)&kv[j * 132 + tx * 8];
            float4 v1 = *(const float4*)&kv[j * 132 + tx * 8 + 4];
            out[0][0]+=p0*v0.x; out[0][1]+=p0*v0.y; out[0][2]+=p0*v0.z; out[0][3]+=p0*v0.w;
            out[0][4]+=p0*v1.x; out[0][5]+=p0*v1.y; out[0][6]+=p0*v1.z; out[0][7]+=p0*v1.w;
            out[1][0]+=p1*v0.x; out[1][1]+=p1*v0.y; out[1][2]+=p1*v0.z; out[1][3]+=p1*v0.w;
            out[1][4]+=p1*v1.x; out[1][5]+=p1*v1.y; out[1][6]+=p1*v1.z; out[1][7]+=p1*v1.w;
            out[2][0]+=p2*v0.x; out[2][1]+=p2*v0.y; out[2][2]+=p2*v0.z; out[2][3]+=p2*v0.w;
            out[2][4]+=p2*v1.x; out[2][5]+=p2*v1.y; out[2][6]+=p2*v1.z; out[2][7]+=p2*v1.w;
            out[3][0]+=p3*v0.x; out[3][1]+=p3*v0.y; out[3][2]+=p3*v0.z; out[3][3]+=p3*v0.w;
            out[3][4]+=p3*v1.x; out[3][5]+=p3*v1.y; out[3][6]+=p3*v1.z; out[3][7]+=p3*v1.w;
        }
        __syncthreads();
    }

    int b = bh >> 5, hh = bh & 31;
    #pragma unroll
    for (int a = 0; a < 4; a++) {
        int tokrow = qt * 64 + ty * 4 + a;
        __half* dst = Oh + ((size_t)(b * SEQ + tokrow)) * DL + hh * HD + tx * 8;
        uint4 r;
        r.x = pack_h2(out[a][0], out[a][1]);
        r.y = pack_h2(out[a][2], out[a][3]);
        r.z = pack_h2(out[a][4], out[a][5]);
        r.w = pack_h2(out[a][6], out[a][7]);
        *(uint4*)dst = r;
    }
}

// ---------------- pooling + output head --------------------------------------
__global__ void pool_kernel(const float* __restrict__ x, float* __restrict__ pooled)
{
    int b = blockIdx.y;
    int d = blockIdx.x * 256 + threadIdx.x;
    const float* p = x + (size_t)b * SEQ * DL + d;
    float s = 0.f;
    for (int t = 0; t < SEQ; t++) s += p[(size_t)t * DL];
    pooled[b * DL + d] = s * (1.0f / SEQ);
}

__global__ void out1_kernel(const float* __restrict__ pooled, const float* __restrict__ W,
                            const float* __restrict__ b1, float* __restrict__ t1)
{
    int o = blockIdx.x * 8 + (threadIdx.x >> 5);
    int lane = threadIdx.x & 31;
    int b = o / DM, j = o % DM;
    const float* p = pooled + (size_t)b * DL;
    float s = 0.f;
    for (int i = lane; i < DL; i += 32) s += p[i] * W[(size_t)i * DM + j];
    for (int off = 16; off; off >>= 1) s += __shfl_down_sync(0xffffffffu, s, off);
    if (!lane) t1[o] = s + b1[j];
}

__global__ void out2_kernel(const float* __restrict__ t1, const float* __restrict__ W2,
                            const float* __restrict__ b2, float* __restrict__ y)
{
    int b = blockIdx.x;
    float s = 0.f;
    for (int j = threadIdx.x; j < DM; j += 256) s += t1[b * DM + j] * W2[j];
    __shared__ float red[8];
    int lane = threadIdx.x & 31, wp = threadIdx.x >> 5;
    for (int o = 16; o; o >>= 1) s += __shfl_down_sync(0xffffffffu, s, o);
    if (!lane) red[wp] = s;
    __syncthreads();
    if (threadIdx.x == 0) {
        float t = 0.f;
        for (int i = 0; i < 8; i++) t += red[i];
        y[b] = t + b2[0];
    }
}

// ---------------- host orchestration -----------------------------------------
extern "C" void kernel_launch(void* const* d_in, const int* in_sizes, int n_in,
                              void* d_out, int out_size)
{
    const float* text = (const float*)d_in[0];
    const float* vis  = (const float*)d_in[1];
    const int*   ids  = (const int*)  d_in[2];
    const float* inW  = (const float*)d_in[3];
    const float* inb  = (const float*)d_in[4];
    const float* etab = (const float*)d_in[5];
    const float* Wq   = (const float*)d_in[6];
    const float* Wk   = (const float*)d_in[7];
    const float* Wv   = (const float*)d_in[8];
    const float* Wo   = (const float*)d_in[9];
    const float* ln1  = (const float*)d_in[10];
    const float* ln2  = (const float*)d_in[11];
    const float* Wg   = (const float*)d_in[12];
    const float* Wu   = (const float*)d_in[13];
    const float* Wd   = (const float*)d_in[14];
    const float* fnw  = (const float*)d_in[15];
    const float* o1W  = (const float*)d_in[16];
    const float* o1b  = (const float*)d_in[17];
    const float* o2W  = (const float*)d_in[18];
    const float* o2b  = (const float*)d_in[19];
    float* y = (float*)d_out;

    float *h, *x, *q, *k, *v, *act, *act2, *tvp, *pooled, *t1;
    __half *xh, *oh, *acth, *tvh;
    __half *inWh, *wqh, *wkh, *wvh, *woh, *wgh, *wuh, *wdh;
    cudaGetSymbolAddress((void**)&h,      g_h);
    cudaGetSymbolAddress((void**)&x,      g_x);
    cudaGetSymbolAddress((void**)&q,      g_q);
    cudaGetSymbolAddress((void**)&k,      g_k);
    cudaGetSymbolAddress((void**)&v,      g_v);
    cudaGetSymbolAddress((void**)&act,    g_act);
    cudaGetSymbolAddress((void**)&act2,   g_act2);
    cudaGetSymbolAddress((void**)&tvp,    g_tvp);
    cudaGetSymbolAddress((void**)&pooled, g_pooled);
    cudaGetSymbolAddress((void**)&t1,     g_t1);
    cudaGetSymbolAddress((void**)&xh,     g_xh);
    cudaGetSymbolAddress((void**)&oh,     g_oh);
    cudaGetSymbolAddress((void**)&acth,   g_acth);
    cudaGetSymbolAddress((void**)&tvh,    g_tvh);
    cudaGetSymbolAddress((void**)&inWh,   g_inWh);
    cudaGetSymbolAddress((void**)&wqh,    g_wqh);
    cudaGetSymbolAddress((void**)&wkh,    g_wkh);
    cudaGetSymbolAddress((void**)&wvh,    g_wvh);
    cudaGetSymbolAddress((void**)&woh,    g_woh);
    cudaGetSymbolAddress((void**)&wgh,    g_wgh);
    cudaGetSymbolAddress((void**)&wuh,    g_wuh);
    cudaGetSymbolAddress((void**)&wdh,    g_wdh);

    cudaFuncSetAttribute(attention_kernel,
                         cudaFuncAttributeMaxDynamicSharedMemorySize, ATT_SMEM);
    cudaFuncSetAttribute(gemm_h<0>, cudaFuncAttributeMaxDynamicSharedMemorySize, GEMM_SMEM);
    cudaFuncSetAttribute(gemm_h<1>, cudaFuncAttributeMaxDynamicSharedMemorySize, GEMM_SMEM);
    cudaFuncSetAttribute(gemm_h<2>, cudaFuncAttributeMaxDynamicSharedMemorySize, GEMM_SMEM);
    cudaFuncSetAttribute(gemm_h<4>, cudaFuncAttributeMaxDynamicSharedMemorySize, GEMM_SMEM);

    // --- weight conversion to fp16 ---
    {
        const int CB = 2048, CT = 256;
        f2h_kernel<<<CB, CT>>>(inW, inWh, (long)DM*DL/4);
        f2h_kernel<<<CB, CT>>>(Wq, wqh, (long)2*DL*DL/4);
        f2h_kernel<<<CB, CT>>>(Wk, wkh, (long)2*DL*DL/4);
        f2h_kernel<<<CB, CT>>>(Wv, wvh, (long)2*DL*DL/4);
        f2h_kernel<<<CB, CT>>>(Wo, woh, (long)2*DL*DL/4);
        f2h_kernel<<<CB, CT>>>(Wg, wgh, (long)2*DL*DFF/4);
        f2h_kernel<<<CB, CT>>>(Wu, wuh, (long)2*DL*DFF/4);
        f2h_kernel<<<CB, CT>>>(Wd, wdh, (long)2*DFF*DL/4);
    }

    // --- embeddings ---
    gather_embed_kernel<<<B_ * SP, 256>>>(ids, etab, h);
    pack_tv_kernel<<<TVTOK, 256>>>(text, vis, tvh);
    gemm_h<2><<<dim3(DL/128, TVTOK/128), 256, GEMM_SMEM>>>(tvh, inWh, inb, tvp, TVTOK, DL, DM);
    scatter_tvp_kernel<<<TVTOK, 256>>>(tvp, h);

    // --- transformer layers ---
    for (int l = 0; l < 2; l++) {
        const __half* wq = wqh + (size_t)l * DL * DL;
        const __half* wk = wkh + (size_t)l * DL * DL;
        const __half* wv = wvh + (size_t)l * DL * DL;
        const __half* wo = woh + (size_t)l * DL * DL;
        const float* l1 = ln1 + (size_t)l * DL;
        const float* l2 = ln2 + (size_t)l * DL;
        const __half* wg = wgh + (size_t)l * DL * DFF;
        const __half* wu = wuh + (size_t)l * DL * DFF;
        const __half* wd = wdh + (size_t)l * DFF * DL;

        rmsnorm_kernel<1><<<TOK, 256>>>(h, l1, nullptr, xh);
        gemm_h<4><<<dim3(DL/128, TOK/128), 256, GEMM_SMEM>>>(xh, wq, nullptr, q, TOK, DL, DL);
        gemm_h<4><<<dim3(DL/128, TOK/128), 256, GEMM_SMEM>>>(xh, wk, nullptr, k, TOK, DL, DL);
        gemm_h<4><<<dim3(DL/128, TOK/128), 256, GEMM_SMEM>>>(xh, wv, nullptr, v, TOK, DL, DL);
        rope_kernel<<<B_ * NH * SEQ, 128>>>(q, k);
        attention_kernel<<<dim3(B_ * NH, SEQ/64), 256, ATT_SMEM>>>(q, k, v, oh);
        gemm_h<1><<<dim3(DL/128, TOK/128), 256, GEMM_SMEM>>>(oh, wo, nullptr, h, TOK, DL, DL);
        rmsnorm_kernel<1><<<TOK, 256>>>(h, l2, nullptr, xh);
        gemm_h<0><<<dim3(DFF/128, TOK/128), 256, GEMM_SMEM>>>(xh, wg, nullptr, act,  TOK, DFF, DL);
        gemm_h<0><<<dim3(DFF/128, TOK/128), 256, GEMM_SMEM>>>(xh, wu, nullptr, act2, TOK, DFF, DL);
        silu_mul_kernel<<<(TOK*DFF/4 + 255)/256, 256>>>(act, act2, acth, TOK*DFF/4);
        gemm_h<1><<<dim3(DL/128, TOK/128), 256, GEMM_SMEM>>>(acth, wd, nullptr, h, TOK, DL, DFF);
    }

    // --- head ---
    rmsnorm_kernel<0><<<TOK, 256>>>(h, fnw, x, nullptr);
    pool_kernel<<<dim3(DL/256, B_), 256>>>(x, pooled);
    out1_kernel<<<(B_ * DM) / 8, 256>>>(pooled, o1W, o1b, t1);
    out2_kernel<<<B_, 256>>>(t1, o2W, o2b, y);
}